// round 12
// baseline (speedup 1.0000x reference)
#include <cuda_runtime.h>
#include <cuda_bf16.h>
#include <math.h>

#define T_LEN    8192
#define VOCAB    50257
#define NCHUNK   9                // key chunks
#define CHUNK    912              // keys per chunk (mult of 8); 9*912 = 8208 >= 8192
#define NQTILE   64               // q CTAs; each CTA = 128 queries (4 warps x 32)
#define NTHREADS 128

// scratch (device globals; no allocation allowed)
__device__ float4 g_qp[T_LEN];                 // q' = QSCALE*(Wk^T Wq) p
__device__ float4 g_p4[T_LEN];                 // (px,py,pz,1) fp32
__device__ float4 g_p4h[T_LEN];                // tf32 hi of p4
__device__ float4 g_p4l[T_LEN];                // tf32 lo of p4
__device__ float  g_part[NCHUNK][T_LEN][4];    // per-chunk (Se*px, Se*py, Se*pz, Se)

__device__ __forceinline__ float ex2f(float x) {
    float r; asm("ex2.approx.f32 %0, %1;" : "=f"(r) : "f"(x)); return r;
}
__device__ __forceinline__ unsigned f2tf32(float x) {
    unsigned r; asm("cvt.rna.tf32.f32 %0, %1;" : "=r"(r) : "f"(x)); return r;
}
// MUFU-path exp2 -> tf32 bits
__device__ __forceinline__ unsigned e2t_mufu(float s) { return f2tf32(ex2f(s)); }

// FMA-pipe exp2: magic-add range reduction (exact integer part), deg-4 Taylor
// on f in [-0.5,0.5] (rel err ~6e-5), exponent re-attached via ALU bit ops.
__device__ __forceinline__ float exp2_poly(float s) {
    const float MAGIC = 12582912.0f;           // 1.5 * 2^23
    float t = s + MAGIC;                       // n = round(s) in low mantissa bits
    float n = t - MAGIC;
    float f = s - n;                           // f in [-0.5, 0.5]
    float p = fmaf(f, 0.00961813f, 0.05550411f);
    p = fmaf(f, p, 0.24022650f);
    p = fmaf(f, p, 0.69314718f);
    p = fmaf(f, p, 1.0f);
    // bits(t) << 23 == n << 23 exactly (low 9 bits of 0x4B400000 are zero)
    unsigned e = __float_as_uint(p) + (__float_as_uint(t) << 23);
    return __uint_as_float(e);
}
__device__ __forceinline__ unsigned e2t_poly(float s) { return f2tf32(exp2_poly(s)); }

__device__ __forceinline__ float dot3(float3 q, float4 p) {
    return fmaf(q.x, p.x, fmaf(q.y, p.y, q.z * p.z));
}

// mma.sync m16n8k8 tf32: D = A*B + C (C==D registers)
__device__ __forceinline__ void mma_tf32(float c[4],
                                         unsigned a0, unsigned a1, unsigned a2, unsigned a3,
                                         unsigned b0, unsigned b1) {
    asm volatile(
        "mma.sync.aligned.m16n8k8.row.col.f32.tf32.tf32.f32 "
        "{%0,%1,%2,%3}, {%4,%5,%6,%7}, {%8,%9}, {%0,%1,%2,%3};"
        : "+f"(c[0]), "+f"(c[1]), "+f"(c[2]), "+f"(c[3])
        : "r"(a0), "r"(a1), "r"(a2), "r"(a3), "r"(b0), "r"(b1));
}

// ---------------------------------------------------------------------------
// Kernel 1: gather + posenc; emit q' (pre-scaled), p4 fp32, and tf32 hi/lo.
// ---------------------------------------------------------------------------
__global__ __launch_bounds__(64)
void prep_kernel(const int* __restrict__ x,
                 const float* __restrict__ emb,
                 const float* __restrict__ Wk,
                 const float* __restrict__ Wq) {
    int t = blockIdx.x * blockDim.x + threadIdx.x;
    if (t >= T_LEN) return;

    int xi = x[t];
    xi = min(max(xi, 0), VOCAB - 1);

    // positional encoding — mirror reference fp32 op order: (6.28f*t)/c
    float a = 6.28f * (float)t;
    float s25, c25;
    sincosf(a / 25.0f, &s25, &c25);
    float p0 = emb[xi * 3 + 0] + c25;
    float p1 = emb[xi * 3 + 1] + s25;
    float p2 = emb[xi * 3 + 2] + sinf(a / 5.0f);

    const float QSCALE = 0.8329465708f;  // log2(e)/sqrt(3)

    // q' = QSCALE * (Wk^T Wq) p
    float q0 = 0.f, q1 = 0.f, q2 = 0.f;
    #pragma unroll
    for (int aa = 0; aa < 3; ++aa) {
        float qq = fmaf(Wq[aa * 3 + 0], p0,
                   fmaf(Wq[aa * 3 + 1], p1, Wq[aa * 3 + 2] * p2));
        q0 = fmaf(Wk[aa * 3 + 0], qq, q0);
        q1 = fmaf(Wk[aa * 3 + 1], qq, q1);
        q2 = fmaf(Wk[aa * 3 + 2], qq, q2);
    }
    g_qp[t] = make_float4(q0 * QSCALE, q1 * QSCALE, q2 * QSCALE, 0.0f);

    float4 p4 = make_float4(p0, p1, p2, 1.0f);
    g_p4[t] = p4;

    float h0 = __uint_as_float(f2tf32(p4.x));
    float h1 = __uint_as_float(f2tf32(p4.y));
    float h2 = __uint_as_float(f2tf32(p4.z));
    g_p4h[t] = make_float4(h0, h1, h2, 1.0f);
    g_p4l[t] = make_float4(__uint_as_float(f2tf32(p4.x - h0)),
                           __uint_as_float(f2tf32(p4.y - h1)),
                           __uint_as_float(f2tf32(p4.z - h2)),
                           0.0f);
}

// ---------------------------------------------------------------------------
// Kernel 2: attention; tensor-core accumulation; exp split 5:3 MUFU:FMA-poly
// to balance the quarter-rate MUFU against the FMA pipe.
// grid = (64, 9) = 576 CTAs x 128 thr. Warp = 32 queries (2 m16n8 tiles),
// 8 keys per step. Pad keys: p4 == 0 -> B columns zero -> contribute nothing.
// ---------------------------------------------------------------------------
__global__ __launch_bounds__(NTHREADS)
void attn_kernel() {
    __shared__ float4 sp [CHUNK];   // fp32 p4 (for dots)
    __shared__ float4 sph[CHUNK];   // tf32 hi bits (as floats)
    __shared__ float4 spl[CHUNK];   // tf32 lo bits

    const int tid  = threadIdx.x;
    const int warp = tid >> 5;
    const int lane = tid & 31;
    const int g    = lane >> 2;     // groupID  (0..7)
    const int tg   = lane & 3;      // threadID in group (0..3)
    const int kbeg = blockIdx.y * CHUNK;

    for (int i = tid; i < CHUNK; i += NTHREADS) {
        int idx = kbeg + i;
        if (idx < T_LEN) {
            sp[i] = g_p4[idx]; sph[i] = g_p4h[idx]; spl[i] = g_p4l[idx];
        } else {
            float4 z = make_float4(0.f, 0.f, 0.f, 0.f);
            sp[i] = z; sph[i] = z; spl[i] = z;
        }
    }
    __syncthreads();

    const int qbase = blockIdx.x * 128 + warp * 32;
    float3 q0, q1, q2, q3;
    { float4 t4 = g_qp[qbase + g     ]; q0 = make_float3(t4.x, t4.y, t4.z); }
    { float4 t4 = g_qp[qbase + g +  8]; q1 = make_float3(t4.x, t4.y, t4.z); }
    { float4 t4 = g_qp[qbase + g + 16]; q2 = make_float3(t4.x, t4.y, t4.z); }
    { float4 t4 = g_qp[qbase + g + 24]; q3 = make_float3(t4.x, t4.y, t4.z); }

    float c0[4] = {0.f, 0.f, 0.f, 0.f};
    float c1[4] = {0.f, 0.f, 0.f, 0.f};

    const float* sphf = (const float*)sph;
    const float* splf = (const float*)spl;

    #pragma unroll 2
    for (int j = 0; j < CHUNK; j += 8) {
        float4 pa = sp[j + tg];
        float4 pb = sp[j + tg + 4];

        // A fragments: 5 exps via MUFU, 3 via FMA-pipe poly (pipe balance)
        unsigned a0 = e2t_mufu(dot3(q0, pa));
        unsigned a1 = e2t_mufu(dot3(q1, pa));
        unsigned a2 = e2t_mufu(dot3(q0, pb));
        unsigned a3 = e2t_mufu(dot3(q1, pb));
        unsigned a4 = e2t_mufu(dot3(q2, pa));
        unsigned a5 = e2t_poly(dot3(q3, pa));
        unsigned a6 = e2t_poly(dot3(q2, pb));
        unsigned a7 = e2t_poly(dot3(q3, pb));

        unsigned bh0 = 0u, bh1 = 0u, bl0 = 0u, bl1 = 0u;
        if (g < 4) {
            bh0 = __float_as_uint(sphf[(j + tg) * 4 + g]);
            bh1 = __float_as_uint(sphf[(j + tg + 4) * 4 + g]);
            bl0 = __float_as_uint(splf[(j + tg) * 4 + g]);
            bl1 = __float_as_uint(splf[(j + tg + 4) * 4 + g]);
        }

        mma_tf32(c0, a0, a1, a2, a3, bh0, bh1);
        mma_tf32(c0, a0, a1, a2, a3, bl0, bl1);
        mma_tf32(c1, a4, a5, a6, a7, bh0, bh1);
        mma_tf32(c1, a4, a5, a6, a7, bl0, bl1);
    }

    if (tg < 2) {
        const int cc = blockIdx.y;
        float2* o;
        o = (float2*)&g_part[cc][qbase + g     ][2 * tg]; *o = make_float2(c0[0], c0[1]);
        o = (float2*)&g_part[cc][qbase + g +  8][2 * tg]; *o = make_float2(c0[2], c0[3]);
        o = (float2*)&g_part[cc][qbase + g + 16][2 * tg]; *o = make_float2(c1[0], c1[1]);
        o = (float2*)&g_part[cc][qbase + g + 24][2 * tg]; *o = make_float2(c1[2], c1[3]);
    }
}

// ---------------------------------------------------------------------------
// Kernel 3: deterministic fixed-order reduce over NCHUNK partials, then Wv
// and divide.
// ---------------------------------------------------------------------------
__global__ __launch_bounds__(256)
void reduce_kernel(const float* __restrict__ Wv, float* __restrict__ out) {
    int t = blockIdx.x * blockDim.x + threadIdx.x;
    if (t >= T_LEN) return;

    float r0 = 0.f, r1 = 0.f, r2 = 0.f, rd = 0.f;
    #pragma unroll
    for (int s = 0; s < NCHUNK; ++s) {
        const float* p = g_part[s][t];
        r0 += p[0]; r1 += p[1]; r2 += p[2]; rd += p[3];
    }
    float inv = 1.0f / rd;
    out[t * 3 + 0] = fmaf(Wv[0], r0, fmaf(Wv[1], r1, Wv[2] * r2)) * inv;
    out[t * 3 + 1] = fmaf(Wv[3], r0, fmaf(Wv[4], r1, Wv[5] * r2)) * inv;
    out[t * 3 + 2] = fmaf(Wv[6], r0, fmaf(Wv[7], r1, Wv[8] * r2)) * inv;
}

extern "C" void kernel_launch(void* const* d_in, const int* in_sizes, int n_in,
                              void* d_out, int out_size) {
    const int*   x   = (const int*)  d_in[0];
    const float* emb = (const float*)d_in[1];
    const float* Wk  = (const float*)d_in[2];
    const float* Wq  = (const float*)d_in[3];
    const float* Wv  = (const float*)d_in[4];
    float* out = (float*)d_out;

    prep_kernel<<<T_LEN / 64, 64>>>(x, emb, Wk, Wq);
    attn_kernel<<<dim3(NQTILE, NCHUNK), NTHREADS>>>();
    reduce_kernel<<<T_LEN / 256, 256>>>(Wv, out);
}

// round 13
// speedup vs baseline: 1.2050x; 1.2050x over previous
#include <cuda_runtime.h>
#include <cuda_fp16.h>
#include <math.h>

#define T_LEN    8192
#define VOCAB    50257
#define NCHUNK   9                // key chunks
#define CHUNK    912              // keys per chunk (mult of 8); 9*912 = 8208 >= 8192
#define NQTILE   64               // q CTAs; each CTA = 128 queries (4 warps x 32)
#define NTHREADS 128

// scratch (device globals; no allocation allowed)
__device__ float4 g_qp[T_LEN];                 // q' = QSCALE*(Wk^T Wq) p
__device__ float4 g_p4[T_LEN];                 // (px,py,pz,1) fp32 (for exact dots)
__device__ __half g_pBh[4][T_LEN];             // f16 hi of (px,py,pz,1)
__device__ __half g_pBl[4][T_LEN];             // f16 lo (residual)
__device__ float  g_part[NCHUNK][T_LEN][4];    // per-chunk (Se*px, Se*py, Se*pz, Se)

// pack two fp32 -> f16x2 {lo, hi}
__device__ __forceinline__ unsigned pack_h2(float lo, float hi) {
    unsigned r; asm("cvt.rn.f16x2.f32 %0, %1, %2;" : "=r"(r) : "f"(hi), "f"(lo)); return r;
}
// two exps per MUFU instruction
__device__ __forceinline__ unsigned h2ex2(unsigned x) {
    unsigned r; asm("ex2.approx.f16x2 %0, %1;" : "=r"(r) : "r"(x)); return r;
}
__device__ __forceinline__ float dot3(float3 q, float4 p) {
    return fmaf(q.x, p.x, fmaf(q.y, p.y, q.z * p.z));
}
// mma m16n8k8 f16 inputs, f32 accum: D = A*B + C (C==D)
__device__ __forceinline__ void mma_f16(float c[4], unsigned a0, unsigned a1, unsigned b0) {
    asm volatile(
        "mma.sync.aligned.m16n8k8.row.col.f32.f16.f16.f32 "
        "{%0,%1,%2,%3}, {%4,%5}, {%6}, {%0,%1,%2,%3};"
        : "+f"(c[0]), "+f"(c[1]), "+f"(c[2]), "+f"(c[3])
        : "r"(a0), "r"(a1), "r"(b0));
}

// ---------------------------------------------------------------------------
// Kernel 1: gather + posenc; emit q' (pre-scaled), p4 fp32, f16 hi/lo of p4.
// ---------------------------------------------------------------------------
__global__ __launch_bounds__(64)
void prep_kernel(const int* __restrict__ x,
                 const float* __restrict__ emb,
                 const float* __restrict__ Wk,
                 const float* __restrict__ Wq) {
    int t = blockIdx.x * blockDim.x + threadIdx.x;
    if (t >= T_LEN) return;

    int xi = x[t];
    xi = min(max(xi, 0), VOCAB - 1);

    // positional encoding — mirror reference fp32 op order: (6.28f*t)/c
    float a = 6.28f * (float)t;
    float s25, c25;
    sincosf(a / 25.0f, &s25, &c25);
    float p0 = emb[xi * 3 + 0] + c25;
    float p1 = emb[xi * 3 + 1] + s25;
    float p2 = emb[xi * 3 + 2] + sinf(a / 5.0f);

    const float QSCALE = 0.8329465708f;  // log2(e)/sqrt(3)

    // q' = QSCALE * (Wk^T Wq) p
    float q0 = 0.f, q1 = 0.f, q2 = 0.f;
    #pragma unroll
    for (int aa = 0; aa < 3; ++aa) {
        float qq = fmaf(Wq[aa * 3 + 0], p0,
                   fmaf(Wq[aa * 3 + 1], p1, Wq[aa * 3 + 2] * p2));
        q0 = fmaf(Wk[aa * 3 + 0], qq, q0);
        q1 = fmaf(Wk[aa * 3 + 1], qq, q1);
        q2 = fmaf(Wk[aa * 3 + 2], qq, q2);
    }
    g_qp[t] = make_float4(q0 * QSCALE, q1 * QSCALE, q2 * QSCALE, 0.0f);

    float pc[4] = {p0, p1, p2, 1.0f};
    g_p4[t] = make_float4(p0, p1, p2, 1.0f);
    #pragma unroll
    for (int c = 0; c < 4; ++c) {
        __half h = __float2half_rn(pc[c]);
        g_pBh[c][t] = h;
        g_pBl[c][t] = __float2half_rn(pc[c] - __half2float(h));
    }
}

// ---------------------------------------------------------------------------
// Kernel 2: attention; exact fp32 scalar dots; f16x2 MUFU exp (2 exps/inst);
// f16 MMA accumulation with B = f16 hi+lo split (p exact to ~22 bits).
// grid = (64, 9) = 576 CTAs x 128 thr. Warp = 32 queries (2 m16n8 tiles).
// Each thread owns keys (j+2tg, j+2tg+1) of every 8-key step — exactly the
// two A-columns its fragment register holds, so packing is layout-free.
// Pad keys: p == 0 -> B columns zero (hi w=0 too) -> contribute nothing.
// ---------------------------------------------------------------------------
__global__ __launch_bounds__(NTHREADS)
void attn_kernel() {
    __shared__ float4 sp[CHUNK];         // fp32 p4 (dots)
    __shared__ __half sBh[4][CHUNK];     // f16 hi, component-major
    __shared__ __half sBl[4][CHUNK];     // f16 lo

    const int tid  = threadIdx.x;
    const int warp = tid >> 5;
    const int lane = tid & 31;
    const int g    = lane >> 2;          // groupID (0..7)
    const int tg   = lane & 3;           // thread-in-group (0..3)
    const int kbeg = blockIdx.y * CHUNK;

    for (int i = tid; i < CHUNK; i += NTHREADS) {
        int idx = kbeg + i;
        if (idx < T_LEN) sp[i] = g_p4[idx];
        else             sp[i] = make_float4(0.f, 0.f, 0.f, 0.f);
    }
    #pragma unroll
    for (int c = 0; c < 4; ++c) {
        for (int i = tid; i < CHUNK; i += NTHREADS) {
            int idx = kbeg + i;
            sBh[c][i] = (idx < T_LEN) ? g_pBh[c][idx] : __half(0.f);
            sBl[c][i] = (idx < T_LEN) ? g_pBl[c][idx] : __half(0.f);
        }
    }
    __syncthreads();

    const int qbase = blockIdx.x * 128 + warp * 32;
    float3 q0, q1, q2, q3;
    { float4 t4 = g_qp[qbase + g     ]; q0 = make_float3(t4.x, t4.y, t4.z); }
    { float4 t4 = g_qp[qbase + g +  8]; q1 = make_float3(t4.x, t4.y, t4.z); }
    { float4 t4 = g_qp[qbase + g + 16]; q2 = make_float3(t4.x, t4.y, t4.z); }
    { float4 t4 = g_qp[qbase + g + 24]; q3 = make_float3(t4.x, t4.y, t4.z); }

    float c0[4] = {0.f, 0.f, 0.f, 0.f};
    float c1[4] = {0.f, 0.f, 0.f, 0.f};

    #pragma unroll 2
    for (int j = 0; j < CHUNK; j += 8) {
        const int ka = j + 2 * tg;          // this thread's two key-columns
        float4 pa = sp[ka];
        float4 pb = sp[ka + 1];

        // scores (exact fp32), packed {lo=col ka, hi=col ka+1}, 2 exps/MUFU-inst
        unsigned a0 = h2ex2(pack_h2(dot3(q0, pa), dot3(q0, pb)));   // rows g
        unsigned a1 = h2ex2(pack_h2(dot3(q1, pa), dot3(q1, pb)));   // rows g+8
        unsigned a2 = h2ex2(pack_h2(dot3(q2, pa), dot3(q2, pb)));   // rows g+16
        unsigned a3 = h2ex2(pack_h2(dot3(q3, pa), dot3(q3, pb)));   // rows g+24

        // B fragment: {B[k=2tg][n=g], B[k=2tg+1][n=g]} = comp g of keys ka, ka+1
        unsigned bh = 0u, bl = 0u;
        if (g < 4) {
            bh = *(const unsigned*)&sBh[g][ka];
            bl = *(const unsigned*)&sBl[g][ka];
        }

        mma_f16(c0, a0, a1, bh);
        mma_f16(c0, a0, a1, bl);
        mma_f16(c1, a2, a3, bh);
        mma_f16(c1, a2, a3, bl);
    }

    // C: c[0]:(g,2tg) c[1]:(g,2tg+1) c[2]:(g+8,2tg) c[3]:(g+8,2tg+1); cols 0..3 real
    if (tg < 2) {
        const int cc = blockIdx.y;
        float2* o;
        o = (float2*)&g_part[cc][qbase + g     ][2 * tg]; *o = make_float2(c0[0], c0[1]);
        o = (float2*)&g_part[cc][qbase + g +  8][2 * tg]; *o = make_float2(c0[2], c0[3]);
        o = (float2*)&g_part[cc][qbase + g + 16][2 * tg]; *o = make_float2(c1[0], c1[1]);
        o = (float2*)&g_part[cc][qbase + g + 24][2 * tg]; *o = make_float2(c1[2], c1[3]);
    }
}

// ---------------------------------------------------------------------------
// Kernel 3: deterministic fixed-order reduce over NCHUNK partials, then Wv
// and divide.
// ---------------------------------------------------------------------------
__global__ __launch_bounds__(256)
void reduce_kernel(const float* __restrict__ Wv, float* __restrict__ out) {
    int t = blockIdx.x * blockDim.x + threadIdx.x;
    if (t >= T_LEN) return;

    float r0 = 0.f, r1 = 0.f, r2 = 0.f, rd = 0.f;
    #pragma unroll
    for (int s = 0; s < NCHUNK; ++s) {
        const float* p = g_part[s][t];
        r0 += p[0]; r1 += p[1]; r2 += p[2]; rd += p[3];
    }
    float inv = 1.0f / rd;
    out[t * 3 + 0] = fmaf(Wv[0], r0, fmaf(Wv[1], r1, Wv[2] * r2)) * inv;
    out[t * 3 + 1] = fmaf(Wv[3], r0, fmaf(Wv[4], r1, Wv[5] * r2)) * inv;
    out[t * 3 + 2] = fmaf(Wv[6], r0, fmaf(Wv[7], r1, Wv[8] * r2)) * inv;
}

extern "C" void kernel_launch(void* const* d_in, const int* in_sizes, int n_in,
                              void* d_out, int out_size) {
    const int*   x   = (const int*)  d_in[0];
    const float* emb = (const float*)d_in[1];
    const float* Wk  = (const float*)d_in[2];
    const float* Wq  = (const float*)d_in[3];
    const float* Wv  = (const float*)d_in[4];
    float* out = (float*)d_out;

    prep_kernel<<<T_LEN / 64, 64>>>(x, emb, Wk, Wq);
    attn_kernel<<<dim3(NQTILE, NCHUNK), NTHREADS>>>();
    reduce_kernel<<<T_LEN / 256, 256>>>(Wv, out);
}

// round 14
// speedup vs baseline: 1.5896x; 1.3192x over previous
#include <cuda_runtime.h>
#include <cuda_fp16.h>
#include <math.h>

#define T_LEN    8192
#define VOCAB    50257
#define NCHUNK   16               // 8192 = 16 * 512 exactly (no padding)
#define CHUNK    512
#define NQTILE   64               // 64 CTAs x 128 queries
#define NTHREADS 128

// scratch (device globals; no allocation allowed)
__device__ float4 g_qt[T_LEN];                 // tf32 bits of q' = QSCALE*(Wk^T Wq)p, w=0
__device__ float4 g_pt[T_LEN];                 // tf32 bits of (px,py,pz,1)
__device__ __half g_pBh[4][T_LEN];             // f16 hi of (px,py,pz,1), component-major
__device__ __half g_pBl[4][T_LEN];             // f16 lo (residual)
__device__ float  g_part[NCHUNK][T_LEN][4];    // per-chunk (Se*px, Se*py, Se*pz, Se)

__device__ __forceinline__ unsigned f2tf32(float x) {
    unsigned r; asm("cvt.rna.tf32.f32 %0, %1;" : "=r"(r) : "f"(x)); return r;
}
// pack two fp32 -> f16x2 {lo, hi}
__device__ __forceinline__ unsigned pack_h2(float lo, float hi) {
    unsigned r; asm("cvt.rn.f16x2.f32 %0, %1, %2;" : "=r"(r) : "f"(hi), "f"(lo)); return r;
}
// two exps per MUFU instruction
__device__ __forceinline__ unsigned h2ex2(unsigned x) {
    unsigned r; asm("ex2.approx.f16x2 %0, %1;" : "=r"(r) : "r"(x)); return r;
}
// S-MMA: m16n8k8 tf32, C = 0 (scores). a2,a3,b1 are zero (k=4..7 padding).
__device__ __forceinline__ void mma_tf32_z(float d[4], unsigned a0, unsigned a1, unsigned b0) {
    asm volatile(
        "mma.sync.aligned.m16n8k8.row.col.f32.tf32.tf32.f32 "
        "{%0,%1,%2,%3}, {%4,%5,%6,%7}, {%8,%9}, {%10,%11,%12,%13};"
        : "=f"(d[0]), "=f"(d[1]), "=f"(d[2]), "=f"(d[3])
        : "r"(a0), "r"(a1), "r"(0u), "r"(0u), "r"(b0), "r"(0u),
          "f"(0.0f), "f"(0.0f), "f"(0.0f), "f"(0.0f));
}
// accum MMA: m16n8k8 f16 inputs, f32 accumulators (C==D)
__device__ __forceinline__ void mma_f16(float c[4], unsigned a0, unsigned a1, unsigned b0) {
    asm volatile(
        "mma.sync.aligned.m16n8k8.row.col.f32.f16.f16.f32 "
        "{%0,%1,%2,%3}, {%4,%5}, {%6}, {%0,%1,%2,%3};"
        : "+f"(c[0]), "+f"(c[1]), "+f"(c[2]), "+f"(c[3])
        : "r"(a0), "r"(a1), "r"(b0));
}

// ---------------------------------------------------------------------------
// Kernel 1: gather + posenc; emit tf32 q', tf32 p, f16 hi/lo of p.
// ---------------------------------------------------------------------------
__global__ __launch_bounds__(64)
void prep_kernel(const int* __restrict__ x,
                 const float* __restrict__ emb,
                 const float* __restrict__ Wk,
                 const float* __restrict__ Wq) {
    int t = blockIdx.x * blockDim.x + threadIdx.x;
    if (t >= T_LEN) return;

    int xi = x[t];
    xi = min(max(xi, 0), VOCAB - 1);

    // positional encoding — mirror reference fp32 op order: (6.28f*t)/c
    float a = 6.28f * (float)t;
    float s25, c25;
    sincosf(a / 25.0f, &s25, &c25);
    float p0 = emb[xi * 3 + 0] + c25;
    float p1 = emb[xi * 3 + 1] + s25;
    float p2 = emb[xi * 3 + 2] + sinf(a / 5.0f);

    const float QSCALE = 0.8329465708f;  // log2(e)/sqrt(3)

    // q' = QSCALE * (Wk^T Wq) p
    float q0 = 0.f, q1 = 0.f, q2 = 0.f;
    #pragma unroll
    for (int aa = 0; aa < 3; ++aa) {
        float qq = fmaf(Wq[aa * 3 + 0], p0,
                   fmaf(Wq[aa * 3 + 1], p1, Wq[aa * 3 + 2] * p2));
        q0 = fmaf(Wk[aa * 3 + 0], qq, q0);
        q1 = fmaf(Wk[aa * 3 + 1], qq, q1);
        q2 = fmaf(Wk[aa * 3 + 2], qq, q2);
    }
    g_qt[t] = make_float4(__uint_as_float(f2tf32(q0 * QSCALE)),
                          __uint_as_float(f2tf32(q1 * QSCALE)),
                          __uint_as_float(f2tf32(q2 * QSCALE)), 0.0f);
    g_pt[t] = make_float4(__uint_as_float(f2tf32(p0)),
                          __uint_as_float(f2tf32(p1)),
                          __uint_as_float(f2tf32(p2)), 1.0f);  // 1.0 exact in tf32

    float pc[4] = {p0, p1, p2, 1.0f};
    #pragma unroll
    for (int c = 0; c < 4; ++c) {
        __half h = __float2half_rn(pc[c]);
        g_pBh[c][t] = h;
        g_pBl[c][t] = __float2half_rn(pc[c] - __half2float(h));
    }
}

// ---------------------------------------------------------------------------
// Kernel 2: attention, fully tensorized. Per 8-key step per warp:
//   S-tile (32q x 8k) via 2 tf32 MMAs (A = q' const in regs, B = p from smem),
//   C-fragment of S == A-fragment of accum MMA (layout identity) ->
//   pack + f16x2 ex2 (2 exps/MUFU-inst) -> 4 f16 accum MMAs (B = p hi+lo).
// grid = (64, 16) = 1024 CTAs x 128 thr, 16.5KB smem -> 7-8 CTAs/SM.
// ---------------------------------------------------------------------------
__global__ __launch_bounds__(NTHREADS, 8)
void attn_kernel() {
    __shared__ float4 sPt[CHUNK];        // tf32 bits of p4
    __shared__ __half sBh[4][CHUNK];     // f16 hi, component-major
    __shared__ __half sBl[4][CHUNK];     // f16 lo

    const int tid  = threadIdx.x;
    const int warp = tid >> 5;
    const int lane = tid & 31;
    const int g    = lane >> 2;          // groupID (0..7)
    const int tg   = lane & 3;           // thread-in-group (0..3)
    const int kbeg = blockIdx.y * CHUNK;

    for (int i = tid; i < CHUNK; i += NTHREADS)
        sPt[i] = g_pt[kbeg + i];
    #pragma unroll
    for (int c = 0; c < 4; ++c) {
        const unsigned* gh = (const unsigned*)&g_pBh[c][kbeg];
        const unsigned* gl = (const unsigned*)&g_pBl[c][kbeg];
        unsigned* sh = (unsigned*)&sBh[c][0];
        unsigned* sl = (unsigned*)&sBl[c][0];
        for (int i = tid; i < CHUNK / 2; i += NTHREADS) {
            sh[i] = gh[i];
            sl[i] = gl[i];
        }
    }
    __syncthreads();

    // constant A-fragments for the S-MMA: component tg of this thread's rows
    const int qbase = blockIdx.x * 128 + warp * 32;
    const float* qtf = (const float*)g_qt;
    unsigned qa0 = __float_as_uint(qtf[(qbase + g     ) * 4 + tg]);
    unsigned qa1 = __float_as_uint(qtf[(qbase + g +  8) * 4 + tg]);
    unsigned qa2 = __float_as_uint(qtf[(qbase + g + 16) * 4 + tg]);
    unsigned qa3 = __float_as_uint(qtf[(qbase + g + 24) * 4 + tg]);

    float c0[4] = {0.f, 0.f, 0.f, 0.f};
    float c1[4] = {0.f, 0.f, 0.f, 0.f};

    const float* sPtf = (const float*)sPt;

    #pragma unroll 4
    for (int j = 0; j < CHUNK; j += 8) {
        // B fragment for S-MMA: component tg of key j+g (n = key, k = component)
        unsigned b0 = __float_as_uint(sPtf[(j + g) * 4 + tg]);

        float s0[4], s1[4];
        mma_tf32_z(s0, qa0, qa1, b0);    // rows g, g+8   x keys j..j+7
        mma_tf32_z(s1, qa2, qa3, b0);    // rows g+16,g+24 x keys j..j+7

        // C layout of S == A layout of f16 MMA: pack cols (2tg, 2tg+1), 2 exps/inst
        unsigned a0 = h2ex2(pack_h2(s0[0], s0[1]));
        unsigned a1 = h2ex2(pack_h2(s0[2], s0[3]));
        unsigned a2 = h2ex2(pack_h2(s1[0], s1[1]));
        unsigned a3 = h2ex2(pack_h2(s1[2], s1[3]));

        // accum B fragment: component g (g<4) of keys j+2tg, j+2tg+1
        unsigned bh = 0u, bl = 0u;
        if (g < 4) {
            bh = *(const unsigned*)&sBh[g][j + 2 * tg];
            bl = *(const unsigned*)&sBl[g][j + 2 * tg];
        }

        mma_f16(c0, a0, a1, bh);
        mma_f16(c0, a0, a1, bl);
        mma_f16(c1, a2, a3, bh);
        mma_f16(c1, a2, a3, bl);
    }

    // C: c[0]:(g,2tg) c[1]:(g,2tg+1) c[2]:(g+8,2tg) c[3]:(g+8,2tg+1); cols 0..3 real
    if (tg < 2) {
        const int cc = blockIdx.y;
        float2* o;
        o = (float2*)&g_part[cc][qbase + g     ][2 * tg]; *o = make_float2(c0[0], c0[1]);
        o = (float2*)&g_part[cc][qbase + g +  8][2 * tg]; *o = make_float2(c0[2], c0[3]);
        o = (float2*)&g_part[cc][qbase + g + 16][2 * tg]; *o = make_float2(c1[0], c1[1]);
        o = (float2*)&g_part[cc][qbase + g + 24][2 * tg]; *o = make_float2(c1[2], c1[3]);
    }
}

// ---------------------------------------------------------------------------
// Kernel 3: deterministic fixed-order reduce over NCHUNK partials, then Wv
// and divide.
// ---------------------------------------------------------------------------
__global__ __launch_bounds__(256)
void reduce_kernel(const float* __restrict__ Wv, float* __restrict__ out) {
    int t = blockIdx.x * blockDim.x + threadIdx.x;
    if (t >= T_LEN) return;

    float r0 = 0.f, r1 = 0.f, r2 = 0.f, rd = 0.f;
    #pragma unroll
    for (int s = 0; s < NCHUNK; ++s) {
        const float* p = g_part[s][t];
        r0 += p[0]; r1 += p[1]; r2 += p[2]; rd += p[3];
    }
    float inv = 1.0f / rd;
    out[t * 3 + 0] = fmaf(Wv[0], r0, fmaf(Wv[1], r1, Wv[2] * r2)) * inv;
    out[t * 3 + 1] = fmaf(Wv[3], r0, fmaf(Wv[4], r1, Wv[5] * r2)) * inv;
    out[t * 3 + 2] = fmaf(Wv[6], r0, fmaf(Wv[7], r1, Wv[8] * r2)) * inv;
}

extern "C" void kernel_launch(void* const* d_in, const int* in_sizes, int n_in,
                              void* d_out, int out_size) {
    const int*   x   = (const int*)  d_in[0];
    const float* emb = (const float*)d_in[1];
    const float* Wk  = (const float*)d_in[2];
    const float* Wq  = (const float*)d_in[3];
    const float* Wv  = (const float*)d_in[4];
    float* out = (float*)d_out;

    prep_kernel<<<T_LEN / 64, 64>>>(x, emb, Wk, Wq);
    attn_kernel<<<dim3(NQTILE, NCHUNK), NTHREADS>>>();
    reduce_kernel<<<T_LEN / 256, 256>>>(Wv, out);
}

// round 15
// speedup vs baseline: 1.5963x; 1.0042x over previous
#include <cuda_runtime.h>
#include <cuda_fp16.h>
#include <math.h>

#define T_LEN    8192
#define VOCAB    50257
#define NCHUNK   16               // 8192 = 16 * 512 exactly (no padding)
#define CHUNK    512
#define NQTILE   64               // 64 CTAs x 128 queries
#define NTHREADS 128

// scratch (device globals; no allocation allowed)
__device__ float4 g_qt[T_LEN];                 // tf32 bits of q' = QSCALE*(Wk^T Wq)p, w=0
__device__ float4 g_pt[T_LEN];                 // tf32 bits of (px,py,pz,1)
__device__ __half g_pBh[4][T_LEN];             // f16 hi of (px,py,pz,1), component-major
__device__ __half g_pBl[4][T_LEN];             // f16 lo (residual)
__device__ float  g_part[NCHUNK][T_LEN][4];    // per-chunk (Se*px, Se*py, Se*pz, Se)

__device__ __forceinline__ unsigned f2tf32(float x) {
    unsigned r; asm("cvt.rna.tf32.f32 %0, %1;" : "=r"(r) : "f"(x)); return r;
}
__device__ __forceinline__ unsigned pack_h2(float lo, float hi) {
    unsigned r; asm("cvt.rn.f16x2.f32 %0, %1, %2;" : "=r"(r) : "f"(hi), "f"(lo)); return r;
}
__device__ __forceinline__ unsigned h2ex2(unsigned x) {
    unsigned r; asm("ex2.approx.f16x2 %0, %1;" : "=r"(r) : "r"(x)); return r;
}
// S-MMA: m16n8k8 tf32, C = 0 (scores). k=4..7 zero-padded.
__device__ __forceinline__ void mma_tf32_z(float d[4], unsigned a0, unsigned a1, unsigned b0) {
    asm volatile(
        "mma.sync.aligned.m16n8k8.row.col.f32.tf32.tf32.f32 "
        "{%0,%1,%2,%3}, {%4,%5,%6,%7}, {%8,%9}, {%10,%11,%12,%13};"
        : "=f"(d[0]), "=f"(d[1]), "=f"(d[2]), "=f"(d[3])
        : "r"(a0), "r"(a1), "r"(0u), "r"(0u), "r"(b0), "r"(0u),
          "f"(0.0f), "f"(0.0f), "f"(0.0f), "f"(0.0f));
}
// accum MMA: m16n8k16 f16 inputs, f32 accumulators (C==D) — 16 keys per inst
__device__ __forceinline__ void mma_f16_k16(float c[4],
                                            unsigned a0, unsigned a1, unsigned a2, unsigned a3,
                                            unsigned b0, unsigned b1) {
    asm volatile(
        "mma.sync.aligned.m16n8k16.row.col.f32.f16.f16.f32 "
        "{%0,%1,%2,%3}, {%4,%5,%6,%7}, {%8,%9}, {%0,%1,%2,%3};"
        : "+f"(c[0]), "+f"(c[1]), "+f"(c[2]), "+f"(c[3])
        : "r"(a0), "r"(a1), "r"(a2), "r"(a3), "r"(b0), "r"(b1));
}

// accurate trig for large args: exact double range-reduction, then fast intrinsic
__device__ __forceinline__ float cos_red(float x) {
    double d = (double)x;
    double r = d - 6.283185307179586 * rint(d * 0.15915494309189535);
    return __cosf((float)r);
}
__device__ __forceinline__ float sin_red(float x) {
    double d = (double)x;
    double r = d - 6.283185307179586 * rint(d * 0.15915494309189535);
    return __sinf((float)r);
}

// ---------------------------------------------------------------------------
// Kernel 1: gather + posenc; emit tf32 q', tf32 p, f16 hi/lo of p.
// Trig via double range-reduction + __cosf/__sinf (avoids Payne-Hanek slow path).
// ---------------------------------------------------------------------------
__global__ __launch_bounds__(64)
void prep_kernel(const int* __restrict__ x,
                 const float* __restrict__ emb,
                 const float* __restrict__ Wk,
                 const float* __restrict__ Wq) {
    int t = blockIdx.x * blockDim.x + threadIdx.x;
    if (t >= T_LEN) return;

    int xi = x[t];
    xi = min(max(xi, 0), VOCAB - 1);

    // positional encoding — mirror reference fp32 op order: (6.28f*t)/c
    float a = 6.28f * (float)t;
    float p0 = emb[xi * 3 + 0] + cos_red(a / 25.0f);
    float p1 = emb[xi * 3 + 1] + sin_red(a / 25.0f);
    float p2 = emb[xi * 3 + 2] + sin_red(a / 5.0f);

    const float QSCALE = 0.8329465708f;  // log2(e)/sqrt(3)

    // q' = QSCALE * (Wk^T Wq) p
    float q0 = 0.f, q1 = 0.f, q2 = 0.f;
    #pragma unroll
    for (int aa = 0; aa < 3; ++aa) {
        float qq = fmaf(Wq[aa * 3 + 0], p0,
                   fmaf(Wq[aa * 3 + 1], p1, Wq[aa * 3 + 2] * p2));
        q0 = fmaf(Wk[aa * 3 + 0], qq, q0);
        q1 = fmaf(Wk[aa * 3 + 1], qq, q1);
        q2 = fmaf(Wk[aa * 3 + 2], qq, q2);
    }
    g_qt[t] = make_float4(__uint_as_float(f2tf32(q0 * QSCALE)),
                          __uint_as_float(f2tf32(q1 * QSCALE)),
                          __uint_as_float(f2tf32(q2 * QSCALE)), 0.0f);
    g_pt[t] = make_float4(__uint_as_float(f2tf32(p0)),
                          __uint_as_float(f2tf32(p1)),
                          __uint_as_float(f2tf32(p2)), 1.0f);

    float pc[4] = {p0, p1, p2, 1.0f};
    #pragma unroll
    for (int c = 0; c < 4; ++c) {
        __half h = __float2half_rn(pc[c]);
        g_pBh[c][t] = h;
        g_pBl[c][t] = __float2half_rn(pc[c] - __half2float(h));
    }
}

// ---------------------------------------------------------------------------
// Kernel 2: attention, fully tensorized, 16 keys per accum MMA.
// Per 16-key step per warp: 4 tf32 S-MMAs -> pack -> f16x2 ex2 -> 4 k16 MMAs.
// grid = (64, 16) = 1024 CTAs x 128 thr, one ~7/SM wave.
// ---------------------------------------------------------------------------
__global__ __launch_bounds__(NTHREADS, 7)
void attn_kernel() {
    __shared__ float4 sPt[CHUNK];        // tf32 bits of p4
    __shared__ __half sBh[4][CHUNK];     // f16 hi, component-major
    __shared__ __half sBl[4][CHUNK];     // f16 lo

    const int tid  = threadIdx.x;
    const int warp = tid >> 5;
    const int lane = tid & 31;
    const int g    = lane >> 2;          // groupID (0..7)
    const int tg   = lane & 3;           // thread-in-group (0..3)
    const int kbeg = blockIdx.y * CHUNK;

    for (int i = tid; i < CHUNK; i += NTHREADS)
        sPt[i] = g_pt[kbeg + i];
    #pragma unroll
    for (int c = 0; c < 4; ++c) {
        const unsigned* gh = (const unsigned*)&g_pBh[c][kbeg];
        const unsigned* gl = (const unsigned*)&g_pBl[c][kbeg];
        unsigned* sh = (unsigned*)&sBh[c][0];
        unsigned* sl = (unsigned*)&sBl[c][0];
        for (int i = tid; i < CHUNK / 2; i += NTHREADS) {
            sh[i] = gh[i];
            sl[i] = gl[i];
        }
    }
    __syncthreads();

    const int qbase = blockIdx.x * 128 + warp * 32;
    const float* qtf = (const float*)g_qt;
    unsigned qa0 = __float_as_uint(qtf[(qbase + g     ) * 4 + tg]);
    unsigned qa1 = __float_as_uint(qtf[(qbase + g +  8) * 4 + tg]);
    unsigned qa2 = __float_as_uint(qtf[(qbase + g + 16) * 4 + tg]);
    unsigned qa3 = __float_as_uint(qtf[(qbase + g + 24) * 4 + tg]);

    float c0[4] = {0.f, 0.f, 0.f, 0.f};
    float c1[4] = {0.f, 0.f, 0.f, 0.f};

    const float* sPtf = (const float*)sPt;

    #pragma unroll 4
    for (int j = 0; j < CHUNK; j += 16) {
        // S B-fragments: component tg of keys j+g and j+8+g
        unsigned b0a = __float_as_uint(sPtf[(j + g) * 4 + tg]);
        unsigned b0b = __float_as_uint(sPtf[(j + 8 + g) * 4 + tg]);

        float s0[4], s1[4], s2[4], s3[4];
        mma_tf32_z(s0, qa0, qa1, b0a);   // rows g,g+8    x keys j..j+7
        mma_tf32_z(s1, qa2, qa3, b0a);   // rows g+16,+24 x keys j..j+7
        mma_tf32_z(s2, qa0, qa1, b0b);   // rows g,g+8    x keys j+8..j+15
        mma_tf32_z(s3, qa2, qa3, b0b);   // rows g+16,+24 x keys j+8..j+15

        // exp fragments: S C-layout == k16 A-layout (a0/a1 = k-lo, a2/a3 = k-hi)
        unsigned a0 = h2ex2(pack_h2(s0[0], s0[1]));
        unsigned a1 = h2ex2(pack_h2(s0[2], s0[3]));
        unsigned a2 = h2ex2(pack_h2(s2[0], s2[1]));
        unsigned a3 = h2ex2(pack_h2(s2[2], s2[3]));
        unsigned a4 = h2ex2(pack_h2(s1[0], s1[1]));
        unsigned a5 = h2ex2(pack_h2(s1[2], s1[3]));
        unsigned a6 = h2ex2(pack_h2(s3[0], s3[1]));
        unsigned a7 = h2ex2(pack_h2(s3[2], s3[3]));

        // accum B fragments: component g (g<4) of keys (j+2tg, j+2tg+1) and +8
        unsigned bh0 = 0u, bh1 = 0u, bl0 = 0u, bl1 = 0u;
        if (g < 4) {
            bh0 = *(const unsigned*)&sBh[g][j + 2 * tg];
            bh1 = *(const unsigned*)&sBh[g][j + 8 + 2 * tg];
            bl0 = *(const unsigned*)&sBl[g][j + 2 * tg];
            bl1 = *(const unsigned*)&sBl[g][j + 8 + 2 * tg];
        }

        mma_f16_k16(c0, a0, a1, a2, a3, bh0, bh1);
        mma_f16_k16(c0, a0, a1, a2, a3, bl0, bl1);
        mma_f16_k16(c1, a4, a5, a6, a7, bh0, bh1);
        mma_f16_k16(c1, a4, a5, a6, a7, bl0, bl1);
    }

    // C: c[0]:(g,2tg) c[1]:(g,2tg+1) c[2]:(g+8,2tg) c[3]:(g+8,2tg+1); cols 0..3 real
    if (tg < 2) {
        const int cc = blockIdx.y;
        float2* o;
        o = (float2*)&g_part[cc][qbase + g     ][2 * tg]; *o = make_float2(c0[0], c0[1]);
        o = (float2*)&g_part[cc][qbase + g +  8][2 * tg]; *o = make_float2(c0[2], c0[3]);
        o = (float2*)&g_part[cc][qbase + g + 16][2 * tg]; *o = make_float2(c1[0], c1[1]);
        o = (float2*)&g_part[cc][qbase + g + 24][2 * tg]; *o = make_float2(c1[2], c1[3]);
    }
}

// ---------------------------------------------------------------------------
// Kernel 3: deterministic fixed-order reduce over NCHUNK partials, then Wv
// and divide.
// ---------------------------------------------------------------------------
__global__ __launch_bounds__(256)
void reduce_kernel(const float* __restrict__ Wv, float* __restrict__ out) {
    int t = blockIdx.x * blockDim.x + threadIdx.x;
    if (t >= T_LEN) return;

    float r0 = 0.f, r1 = 0.f, r2 = 0.f, rd = 0.f;
    #pragma unroll
    for (int s = 0; s < NCHUNK; ++s) {
        const float* p = g_part[s][t];
        r0 += p[0]; r1 += p[1]; r2 += p[2]; rd += p[3];
    }
    float inv = 1.0f / rd;
    out[t * 3 + 0] = fmaf(Wv[0], r0, fmaf(Wv[1], r1, Wv[2] * r2)) * inv;
    out[t * 3 + 1] = fmaf(Wv[3], r0, fmaf(Wv[4], r1, Wv[5] * r2)) * inv;
    out[t * 3 + 2] = fmaf(Wv[6], r0, fmaf(Wv[7], r1, Wv[8] * r2)) * inv;
}

extern "C" void kernel_launch(void* const* d_in, const int* in_sizes, int n_in,
                              void* d_out, int out_size) {
    const int*   x   = (const int*)  d_in[0];
    const float* emb = (const float*)d_in[1];
    const float* Wk  = (const float*)d_in[2];
    const float* Wq  = (const float*)d_in[3];
    const float* Wv  = (const float*)d_in[4];
    float* out = (float*)d_out;

    prep_kernel<<<T_LEN / 64, 64>>>(x, emb, Wk, Wq);
    attn_kernel<<<dim3(NQTILE, NCHUNK), NTHREADS>>>();
    reduce_kernel<<<T_LEN / 256, 256>>>(Wv, out);
}

// round 16
// speedup vs baseline: 1.6477x; 1.0322x over previous
#include <cuda_runtime.h>
#include <cuda_fp16.h>
#include <math.h>

#define T_LEN    8192
#define VOCAB    50257
#define NCHUNK   16               // 8192 = 16 * 512 exactly (no padding)
#define CHUNK    512
#define NQTILE   64               // 64 CTAs x 128 queries
#define NTHREADS 128

// scratch (device globals; no allocation allowed)
__device__ float4 g_qt[T_LEN];                 // tf32 bits of q' = QSCALE*(Wk^T Wq)p, w=0
__device__ float4 g_pt[T_LEN];                 // tf32 bits of (px,py,pz,1)
__device__ __half g_pBh[4][T_LEN];             // f16 hi of (px,py,pz,1), component-major
__device__ __half g_pBl[4][T_LEN];             // f16 lo (residual)
__device__ float  g_part[NCHUNK][T_LEN][4];    // per-chunk (Se*px, Se*py, Se*pz, Se)
__device__ unsigned g_cnt2[NQTILE];            // monotonic arrival counters (mod-16)

__device__ __forceinline__ unsigned f2tf32(float x) {
    unsigned r; asm("cvt.rna.tf32.f32 %0, %1;" : "=r"(r) : "f"(x)); return r;
}
__device__ __forceinline__ unsigned pack_h2(float lo, float hi) {
    unsigned r; asm("cvt.rn.f16x2.f32 %0, %1, %2;" : "=r"(r) : "f"(hi), "f"(lo)); return r;
}
__device__ __forceinline__ unsigned h2ex2(unsigned x) {
    unsigned r; asm("ex2.approx.f16x2 %0, %1;" : "=r"(r) : "r"(x)); return r;
}
// S-MMA: m16n8k8 tf32, C = 0 (scores). k=4..7 zero-padded.
__device__ __forceinline__ void mma_tf32_z(float d[4], unsigned a0, unsigned a1, unsigned b0) {
    asm volatile(
        "mma.sync.aligned.m16n8k8.row.col.f32.tf32.tf32.f32 "
        "{%0,%1,%2,%3}, {%4,%5,%6,%7}, {%8,%9}, {%10,%11,%12,%13};"
        : "=f"(d[0]), "=f"(d[1]), "=f"(d[2]), "=f"(d[3])
        : "r"(a0), "r"(a1), "r"(0u), "r"(0u), "r"(b0), "r"(0u),
          "f"(0.0f), "f"(0.0f), "f"(0.0f), "f"(0.0f));
}
// accum MMA: m16n8k16 f16 inputs, f32 accumulators (C==D) — 16 keys per inst
__device__ __forceinline__ void mma_f16_k16(float c[4],
                                            unsigned a0, unsigned a1, unsigned a2, unsigned a3,
                                            unsigned b0, unsigned b1) {
    asm volatile(
        "mma.sync.aligned.m16n8k16.row.col.f32.f16.f16.f32 "
        "{%0,%1,%2,%3}, {%4,%5,%6,%7}, {%8,%9}, {%0,%1,%2,%3};"
        : "+f"(c[0]), "+f"(c[1]), "+f"(c[2]), "+f"(c[3])
        : "r"(a0), "r"(a1), "r"(a2), "r"(a3), "r"(b0), "r"(b1));
}

// fp32 Cody-Waite range reduction (n <= 328) + fast intrinsic trig.
// 2pi = 6.28125 (=201/32, so n*c1 exact) + 0.0019353072; residual ~3e-8*n.
__device__ __forceinline__ float red2pi(float x) {
    float n = rintf(x * 0.15915494309f);
    float r = fmaf(n, -6.28125f, x);
    return fmaf(n, -0.0019353072f, r);
}
__device__ __forceinline__ float cos_red(float x) { return __cosf(red2pi(x)); }
__device__ __forceinline__ float sin_red(float x) { return __sinf(red2pi(x)); }

// ---------------------------------------------------------------------------
// Kernel 1: gather + posenc; emit tf32 q', tf32 p, f16 hi/lo of p.
// All-fp32 trig path (no FP64, no Payne-Hanek).
// ---------------------------------------------------------------------------
__global__ __launch_bounds__(64)
void prep_kernel(const int* __restrict__ x,
                 const float* __restrict__ emb,
                 const float* __restrict__ Wk,
                 const float* __restrict__ Wq) {
    int t = blockIdx.x * blockDim.x + threadIdx.x;
    if (t >= T_LEN) return;

    int xi = x[t];
    xi = min(max(xi, 0), VOCAB - 1);

    // positional encoding — mirror reference fp32 op order: (6.28f*t)/c
    float a = 6.28f * (float)t;
    float p0 = emb[xi * 3 + 0] + cos_red(a / 25.0f);
    float p1 = emb[xi * 3 + 1] + sin_red(a / 25.0f);
    float p2 = emb[xi * 3 + 2] + sin_red(a / 5.0f);

    const float QSCALE = 0.8329465708f;  // log2(e)/sqrt(3)

    // q' = QSCALE * (Wk^T Wq) p
    float q0 = 0.f, q1 = 0.f, q2 = 0.f;
    #pragma unroll
    for (int aa = 0; aa < 3; ++aa) {
        float qq = fmaf(Wq[aa * 3 + 0], p0,
                   fmaf(Wq[aa * 3 + 1], p1, Wq[aa * 3 + 2] * p2));
        q0 = fmaf(Wk[aa * 3 + 0], qq, q0);
        q1 = fmaf(Wk[aa * 3 + 1], qq, q1);
        q2 = fmaf(Wk[aa * 3 + 2], qq, q2);
    }
    g_qt[t] = make_float4(__uint_as_float(f2tf32(q0 * QSCALE)),
                          __uint_as_float(f2tf32(q1 * QSCALE)),
                          __uint_as_float(f2tf32(q2 * QSCALE)), 0.0f);
    g_pt[t] = make_float4(__uint_as_float(f2tf32(p0)),
                          __uint_as_float(f2tf32(p1)),
                          __uint_as_float(f2tf32(p2)), 1.0f);

    float pc[4] = {p0, p1, p2, 1.0f};
    #pragma unroll
    for (int c = 0; c < 4; ++c) {
        __half h = __float2half_rn(pc[c]);
        g_pBh[c][t] = h;
        g_pBl[c][t] = __float2half_rn(pc[c] - __half2float(h));
    }
}

// ---------------------------------------------------------------------------
// Kernel 2: attention, fully tensorized, + fused tail reduce.
// Per 16-key step per warp: 4 tf32 S-MMAs -> pack -> f16x2 ex2 -> 4 k16 MMAs.
// Tail: last-arriving of the 16 chunk-CTAs per qtile reduces its own 128
// queries with all 128 threads (16 independent float4 loads each, fixed
// order -> deterministic; monotonic mod-16 counter -> graph-replay safe).
// ---------------------------------------------------------------------------
__global__ __launch_bounds__(NTHREADS, 7)
void attn_kernel(const float* __restrict__ Wv, float* __restrict__ out) {
    __shared__ float4 sPt[CHUNK];        // tf32 bits of p4
    __shared__ __half sBh[4][CHUNK];     // f16 hi, component-major
    __shared__ __half sBl[4][CHUNK];     // f16 lo
    __shared__ unsigned s_old;

    const int tid  = threadIdx.x;
    const int warp = tid >> 5;
    const int lane = tid & 31;
    const int g    = lane >> 2;          // groupID (0..7)
    const int tg   = lane & 3;           // thread-in-group (0..3)
    const int kbeg = blockIdx.y * CHUNK;

    for (int i = tid; i < CHUNK; i += NTHREADS)
        sPt[i] = g_pt[kbeg + i];
    #pragma unroll
    for (int c = 0; c < 4; ++c) {
        const unsigned* gh = (const unsigned*)&g_pBh[c][kbeg];
        const unsigned* gl = (const unsigned*)&g_pBl[c][kbeg];
        unsigned* sh = (unsigned*)&sBh[c][0];
        unsigned* sl = (unsigned*)&sBl[c][0];
        for (int i = tid; i < CHUNK / 2; i += NTHREADS) {
            sh[i] = gh[i];
            sl[i] = gl[i];
        }
    }
    __syncthreads();

    const int qbase = blockIdx.x * 128 + warp * 32;
    const float* qtf = (const float*)g_qt;
    unsigned qa0 = __float_as_uint(qtf[(qbase + g     ) * 4 + tg]);
    unsigned qa1 = __float_as_uint(qtf[(qbase + g +  8) * 4 + tg]);
    unsigned qa2 = __float_as_uint(qtf[(qbase + g + 16) * 4 + tg]);
    unsigned qa3 = __float_as_uint(qtf[(qbase + g + 24) * 4 + tg]);

    float c0[4] = {0.f, 0.f, 0.f, 0.f};
    float c1[4] = {0.f, 0.f, 0.f, 0.f};

    const float* sPtf = (const float*)sPt;

    #pragma unroll 4
    for (int j = 0; j < CHUNK; j += 16) {
        unsigned b0a = __float_as_uint(sPtf[(j + g) * 4 + tg]);
        unsigned b0b = __float_as_uint(sPtf[(j + 8 + g) * 4 + tg]);

        float s0[4], s1[4], s2[4], s3[4];
        mma_tf32_z(s0, qa0, qa1, b0a);   // rows g,g+8    x keys j..j+7
        mma_tf32_z(s1, qa2, qa3, b0a);   // rows g+16,+24 x keys j..j+7
        mma_tf32_z(s2, qa0, qa1, b0b);   // rows g,g+8    x keys j+8..j+15
        mma_tf32_z(s3, qa2, qa3, b0b);   // rows g+16,+24 x keys j+8..j+15

        unsigned a0 = h2ex2(pack_h2(s0[0], s0[1]));
        unsigned a1 = h2ex2(pack_h2(s0[2], s0[3]));
        unsigned a2 = h2ex2(pack_h2(s2[0], s2[1]));
        unsigned a3 = h2ex2(pack_h2(s2[2], s2[3]));
        unsigned a4 = h2ex2(pack_h2(s1[0], s1[1]));
        unsigned a5 = h2ex2(pack_h2(s1[2], s1[3]));
        unsigned a6 = h2ex2(pack_h2(s3[0], s3[1]));
        unsigned a7 = h2ex2(pack_h2(s3[2], s3[3]));

        unsigned bh0 = 0u, bh1 = 0u, bl0 = 0u, bl1 = 0u;
        if (g < 4) {
            bh0 = *(const unsigned*)&sBh[g][j + 2 * tg];
            bh1 = *(const unsigned*)&sBh[g][j + 8 + 2 * tg];
            bl0 = *(const unsigned*)&sBl[g][j + 2 * tg];
            bl1 = *(const unsigned*)&sBl[g][j + 8 + 2 * tg];
        }

        mma_f16_k16(c0, a0, a1, a2, a3, bh0, bh1);
        mma_f16_k16(c0, a0, a1, a2, a3, bl0, bl1);
        mma_f16_k16(c1, a4, a5, a6, a7, bh0, bh1);
        mma_f16_k16(c1, a4, a5, a6, a7, bl0, bl1);
    }

    // C: c[0]:(g,2tg) c[1]:(g,2tg+1) c[2]:(g+8,2tg) c[3]:(g+8,2tg+1); cols 0..3 real
    if (tg < 2) {
        const int cc = blockIdx.y;
        float2* o;
        o = (float2*)&g_part[cc][qbase + g     ][2 * tg]; *o = make_float2(c0[0], c0[1]);
        o = (float2*)&g_part[cc][qbase + g +  8][2 * tg]; *o = make_float2(c0[2], c0[3]);
        o = (float2*)&g_part[cc][qbase + g + 16][2 * tg]; *o = make_float2(c1[0], c1[1]);
        o = (float2*)&g_part[cc][qbase + g + 24][2 * tg]; *o = make_float2(c1[2], c1[3]);
    }

    // ---- fused tail reduce: last-arriving chunk-CTA per qtile ----
    __threadfence();                     // partials visible before counter bump
    __syncthreads();                     // all warps' stores issued
    if (tid == 0)
        s_old = atomicAdd(&g_cnt2[blockIdx.x], 1u);
    __syncthreads();

    if (s_old % NCHUNK == NCHUNK - 1) {
        int qq = blockIdx.x * 128 + tid;             // one query per thread
        float r0 = 0.f, r1 = 0.f, r2 = 0.f, rd = 0.f;
        #pragma unroll
        for (int s = 0; s < NCHUNK; ++s) {           // fixed order: deterministic
            float4 p = *(const float4*)&g_part[s][qq][0];
            r0 += p.x; r1 += p.y; r2 += p.z; rd += p.w;
        }
        float inv = 1.0f / rd;
        out[qq * 3 + 0] = fmaf(Wv[0], r0, fmaf(Wv[1], r1, Wv[2] * r2)) * inv;
        out[qq * 3 + 1] = fmaf(Wv[3], r0, fmaf(Wv[4], r1, Wv[5] * r2)) * inv;
        out[qq * 3 + 2] = fmaf(Wv[6], r0, fmaf(Wv[7], r1, Wv[8] * r2)) * inv;
    }
}

extern "C" void kernel_launch(void* const* d_in, const int* in_sizes, int n_in,
                              void* d_out, int out_size) {
    const int*   x   = (const int*)  d_in[0];
    const float* emb = (const float*)d_in[1];
    const float* Wk  = (const float*)d_in[2];
    const float* Wq  = (const float*)d_in[3];
    const float* Wv  = (const float*)d_in[4];
    float* out = (float*)d_out;

    prep_kernel<<<T_LEN / 64, 64>>>(x, emb, Wk, Wq);
    attn_kernel<<<dim3(NQTILE, NCHUNK), NTHREADS>>>(Wv, out);
}